// round 3
// baseline (speedup 1.0000x reference)
#include <cuda_runtime.h>
#include <cuda_bf16.h>
#include <cstdint>
#include <cstddef>

// ---------------- problem constants (fixed shapes) ----------------
#define NB 8
#define NQ 300
#define NM 100
#define NCLS 81
#define HW 16384
#define QPAD 384           // 3 tiles of 128 queries
#define MPAD 128           // gt padded to 128 for N dim
#define KSPLIT 4
#define KLEN (HW / KSPLIT) // 4096 bf16 per K-split
#define BK 64              // K tile (bf16 elems) = 128B row
#define KT (KLEN / BK)     // 64 iterations

// ---------------- static device scratch (no allocations allowed) ----------------
__device__ __nv_bfloat16 g_PM[(size_t)NB * QPAD * HW];   // sigmoid(pred_masks), bf16
__device__ __nv_bfloat16 g_GM[(size_t)NB * MPAD * HW];   // gt_masks, bf16
__device__ float g_NUM[(size_t)KSPLIT * NB * NQ * NM];   // partial dot products
__device__ float g_pm_sum[NB * NQ];
__device__ float g_gm_sum[NB * NM];

// ===================== kernel 1: sigmoid + bf16 convert + row sums =====================
__global__ void __launch_bounds__(256) k_convert_pred(const float* __restrict__ pm) {
    int bq = blockIdx.x;                       // 0..2399
    int b = bq / NQ, q = bq - b * NQ;
    const float4* src = reinterpret_cast<const float4*>(pm + (size_t)bq * HW);
    __nv_bfloat162* dst =
        reinterpret_cast<__nv_bfloat162*>(g_PM + ((size_t)b * QPAD + q) * HW);
    float sum = 0.f;
    for (int i = threadIdx.x; i < HW / 4; i += 256) {
        float4 v = src[i];
        float s0 = 1.f / (1.f + __expf(-v.x));
        float s1 = 1.f / (1.f + __expf(-v.y));
        float s2 = 1.f / (1.f + __expf(-v.z));
        float s3 = 1.f / (1.f + __expf(-v.w));
        sum += (s0 + s1) + (s2 + s3);
        dst[2 * i]     = __floats2bfloat162_rn(s0, s1);
        dst[2 * i + 1] = __floats2bfloat162_rn(s2, s3);
    }
    for (int o = 16; o; o >>= 1) sum += __shfl_down_sync(0xffffffffu, sum, o);
    __shared__ float ws[8];
    if ((threadIdx.x & 31) == 0) ws[threadIdx.x >> 5] = sum;
    __syncthreads();
    if (threadIdx.x == 0) {
        float t = 0.f;
        #pragma unroll
        for (int w = 0; w < 8; ++w) t += ws[w];
        g_pm_sum[bq] = t;
    }
}

__global__ void __launch_bounds__(256) k_convert_gt(const float* __restrict__ gm) {
    int bm = blockIdx.x;                       // 0..799
    int b = bm / NM, m = bm - b * NM;
    const float4* src = reinterpret_cast<const float4*>(gm + (size_t)bm * HW);
    __nv_bfloat162* dst =
        reinterpret_cast<__nv_bfloat162*>(g_GM + ((size_t)b * MPAD + m) * HW);
    float sum = 0.f;
    for (int i = threadIdx.x; i < HW / 4; i += 256) {
        float4 v = src[i];
        sum += (v.x + v.y) + (v.z + v.w);
        dst[2 * i]     = __floats2bfloat162_rn(v.x, v.y);
        dst[2 * i + 1] = __floats2bfloat162_rn(v.z, v.w);
    }
    for (int o = 16; o; o >>= 1) sum += __shfl_down_sync(0xffffffffu, sum, o);
    __shared__ float ws[8];
    if ((threadIdx.x & 31) == 0) ws[threadIdx.x >> 5] = sum;
    __syncthreads();
    if (threadIdx.x == 0) {
        float t = 0.f;
        #pragma unroll
        for (int w = 0; w < 8; ++w) t += ws[w];
        g_gm_sum[bm] = t;
    }
}

// ===================== kernel 2: mma.sync bf16 GEMM (dice numerator) =====================
#define TILE_BYTES 16384          // 128 rows x 128B
#define GEMM_SMEM (4 * TILE_BYTES)

__device__ __forceinline__ uint32_t sw128(uint32_t off) {
    return off ^ ((off >> 3) & 0x70);
}

__device__ __forceinline__ void cp_tile(const __nv_bfloat16* __restrict__ src,
                                        uint32_t dstBase) {
    int t = threadIdx.x;
    #pragma unroll
    for (int s = 0; s < 4; ++s) {
        int i = t + s * 256;                  // 0..1023
        int row = i >> 3, c16 = i & 7;
        unsigned long long g =
            __cvta_generic_to_global(src + (size_t)row * HW + c16 * 8);
        uint32_t off = sw128((uint32_t)(row * 128 + c16 * 16));
        asm volatile("cp.async.cg.shared.global [%0], [%1], 16;"
                     :: "r"(dstBase + off), "l"(g));
    }
}

__global__ void __launch_bounds__(256) k_mask_gemm() {
    extern __shared__ char smem[];
    uint32_t sA = (uint32_t)__cvta_generic_to_shared(smem);
    uint32_t sB = sA + 2 * TILE_BYTES;

    int tid = threadIdx.x, lane = tid & 31, warp = tid >> 5;
    int wm = warp & 1, wn = warp >> 1;        // 2 x 4 warp grid
    int warpRow = wm * 64, warpCol = wn * 32;

    int tile = blockIdx.x, b = blockIdx.y, ks = blockIdx.z;
    int q0 = tile * 128;

    const __nv_bfloat16* Abase = g_PM + ((size_t)b * QPAD + q0) * HW + (size_t)ks * KLEN;
    const __nv_bfloat16* Bbase = g_GM + (size_t)b * MPAD * HW + (size_t)ks * KLEN;

    float acc[4][4][4];
    #pragma unroll
    for (int i = 0; i < 4; ++i)
        #pragma unroll
        for (int j = 0; j < 4; ++j)
            #pragma unroll
            for (int r = 0; r < 4; ++r) acc[i][j][r] = 0.f;

    cp_tile(Abase, sA);
    cp_tile(Bbase, sB);
    asm volatile("cp.async.commit_group;");
    asm volatile("cp.async.wait_group 0;");
    __syncthreads();

    int rA = warpRow + (lane & 15);
    int cAsel = lane >> 4;
    int rB = warpCol + (lane & 7);
    int cBsel = (lane >> 3) & 1;

    int st = 0;
    for (int kt = 0; kt < KT; ++kt) {
        if (kt + 1 < KT) {
            int nst = st ^ 1;
            cp_tile(Abase + (size_t)(kt + 1) * BK, sA + nst * TILE_BYTES);
            cp_tile(Bbase + (size_t)(kt + 1) * BK, sB + nst * TILE_BYTES);
            asm volatile("cp.async.commit_group;");
        }
        uint32_t a0 = sA + st * TILE_BYTES;
        uint32_t b0 = sB + st * TILE_BYTES;

        #pragma unroll
        for (int kk = 0; kk < 4; ++kk) {
            uint32_t af[4][4], bf[4][2];
            #pragma unroll
            for (int mt = 0; mt < 4; ++mt) {
                uint32_t addr = a0 + sw128((uint32_t)((rA + mt * 16) * 128
                                                      + (kk * 2 + cAsel) * 16));
                asm volatile("ldmatrix.sync.aligned.m8n8.x4.shared.b16 "
                             "{%0,%1,%2,%3}, [%4];"
                             : "=r"(af[mt][0]), "=r"(af[mt][1]),
                               "=r"(af[mt][2]), "=r"(af[mt][3]) : "r"(addr));
            }
            #pragma unroll
            for (int nt = 0; nt < 4; ++nt) {
                uint32_t addr = b0 + sw128((uint32_t)((rB + nt * 8) * 128
                                                      + (kk * 2 + cBsel) * 16));
                asm volatile("ldmatrix.sync.aligned.m8n8.x2.shared.b16 "
                             "{%0,%1}, [%2];"
                             : "=r"(bf[nt][0]), "=r"(bf[nt][1]) : "r"(addr));
            }
            #pragma unroll
            for (int mt = 0; mt < 4; ++mt)
                #pragma unroll
                for (int nt = 0; nt < 4; ++nt) {
                    asm volatile(
                        "mma.sync.aligned.m16n8k16.row.col.f32.bf16.bf16.f32 "
                        "{%0,%1,%2,%3}, {%4,%5,%6,%7}, {%8,%9}, {%0,%1,%2,%3};"
                        : "+f"(acc[mt][nt][0]), "+f"(acc[mt][nt][1]),
                          "+f"(acc[mt][nt][2]), "+f"(acc[mt][nt][3])
                        : "r"(af[mt][0]), "r"(af[mt][1]),
                          "r"(af[mt][2]), "r"(af[mt][3]),
                          "r"(bf[nt][0]), "r"(bf[nt][1]));
                }
        }
        if (kt + 1 < KT) {
            asm volatile("cp.async.wait_group 0;");
        }
        __syncthreads();
        st ^= 1;
    }

    float* dst = g_NUM + ((size_t)ks * NB + b) * NQ * NM;
    int rowInTile = lane >> 2;
    int colInTile = (lane & 3) * 2;
    #pragma unroll
    for (int mt = 0; mt < 4; ++mt) {
        #pragma unroll
        for (int nt = 0; nt < 4; ++nt) {
            int qb = q0 + warpRow + mt * 16 + rowInTile;
            int mb = warpCol + nt * 8 + colInTile;
            #pragma unroll
            for (int r = 0; r < 4; ++r) {
                int q = qb + ((r >> 1) ? 8 : 0);
                int m = mb + (r & 1);
                if (q < NQ && m < NM)
                    dst[(size_t)q * NM + m] = acc[mt][nt][r];
            }
        }
    }
}

// ===================== kernel 3: assemble full cost matrix =====================
__global__ void __launch_bounds__(128) k_finalize(const float* __restrict__ logits,
                                                  const float* __restrict__ pboxes,
                                                  const int* __restrict__ glabels,
                                                  const float* __restrict__ gboxes,
                                                  float* __restrict__ out) {
    int q = blockIdx.x, b = blockIdx.y;
    int tid = threadIdx.x;
    __shared__ float probs[NCLS];
    __shared__ float red[128];

    const float* lg = logits + ((size_t)b * NQ + q) * NCLS;
    float x = (tid < NCLS) ? lg[tid] : -3.0e38f;
    red[tid] = x; __syncthreads();
    #pragma unroll
    for (int s = 64; s > 0; s >>= 1) { if (tid < s) red[tid] = fmaxf(red[tid], red[tid + s]); __syncthreads(); }
    float mx = red[0]; __syncthreads();
    float e = (tid < NCLS) ? __expf(x - mx) : 0.f;
    red[tid] = e; __syncthreads();
    #pragma unroll
    for (int s = 64; s > 0; s >>= 1) { if (tid < s) red[tid] += red[tid + s]; __syncthreads(); }
    float inv = 1.f / red[0];
    if (tid < NCLS) probs[tid] = e * inv;
    __syncthreads();

    const float* pb = pboxes + ((size_t)b * NQ + q) * 4;
    float px1 = pb[0], py1 = pb[1], px2 = pb[2], py2 = pb[3];
    float pa = (px2 - px1) * (py2 - py1);
    float psum = g_pm_sum[b * NQ + q];
    const size_t NSTR = (size_t)NB * NQ * NM;

    for (int m = tid; m < NM; m += 128) {
        int lbl = glabels[b * NM + m];
        float cclass = -probs[lbl];
        const float* gb = gboxes + ((size_t)b * NM + m) * 4;
        float gx1 = gb[0], gy1 = gb[1], gx2 = gb[2], gy2 = gb[3];
        float l1 = fabsf(px1 - gx1) + fabsf(py1 - gy1) + fabsf(px2 - gx2) + fabsf(py2 - gy2);
        float iw = fmaxf(fminf(px2, gx2) - fmaxf(px1, gx1), 0.f);
        float ih = fmaxf(fminf(py2, gy2) - fmaxf(py1, gy1), 0.f);
        float inter = iw * ih;
        float ga = (gx2 - gx1) * (gy2 - gy1);
        float uni = pa + ga - inter;
        float iou = inter / (uni + 1e-6f);
        float ew = fmaxf(fmaxf(px2, gx2) - fminf(px1, gx1), 0.f);
        float eh = fmaxf(fmaxf(py2, gy2) - fminf(py1, gy1), 0.f);
        float am = ew * eh;
        float giou = iou - (am - uni) / (am + 1e-6f);
        size_t ni = ((size_t)b * NQ + q) * NM + m;
        float dot = g_NUM[ni] + g_NUM[NSTR + ni] + g_NUM[2 * NSTR + ni] + g_NUM[3 * NSTR + ni];
        float den = psum + g_gm_sum[b * NM + m];
        float cmask = 1.f - (2.f * dot) / (den + 1e-6f);
        out[ni] = cclass + 5.f * (l1 - giou) + 2.f * cmask;
    }
}

// ===================== kernel 4: single-warp Jonker-Volgenant (exact, f64) =====================
// Shared: u[100] f64, cost[100][300] f32 (transposed), p[300], way[300].
// Warp 0 solves; lanes hold v/minv/used for 10 columns each in registers.
#define HUNG_THREADS 512
#define HUNG_SMEM (NM * 8 + NM * NQ * 4 + NQ * 4 * 2)
#define NSLOT 10

__global__ void __launch_bounds__(HUNG_THREADS) k_hungarian(float* __restrict__ out, int out_size) {
    extern __shared__ char sm[];
    double* u   = reinterpret_cast<double*>(sm);              // [100]
    float* cost = reinterpret_cast<float*>(u + NM);           // [100][300]
    int* p      = reinterpret_cast<int*>(cost + NM * NQ);     // [300]
    int* way    = p + NQ;                                     // [300]

    int b = blockIdx.x;
    int tid = threadIdx.x;
    const float* C = out + (size_t)b * NQ * NM;

    // cooperative transpose load: cost[m][q] = C[q][m]
    for (int idx = tid; idx < NM * NQ; idx += HUNG_THREADS) {
        int q = idx / NM, m = idx - q * NM;
        cost[m * NQ + q] = C[idx];
    }
    for (int j = tid; j < NQ; j += HUNG_THREADS) p[j] = -1;
    for (int i = tid; i < NM; i += HUNG_THREADS) u[i] = 0.0;
    __syncthreads();
    if (tid >= 32) return;

    int lane = tid;
    double vv[NSLOT], minv[NSLOT];
    #pragma unroll
    for (int s = 0; s < NSLOT; ++s) vv[s] = 0.0;
    // slot validity: s<9 always, s==9 only lanes 0..11
    const bool valid9 = (lane < 12);

    for (int i = 0; i < NM; ++i) {
        unsigned usedmask = 0;
        #pragma unroll
        for (int s = 0; s < NSLOT; ++s) minv[s] = 1.0e300;
        int cr = i, j0 = -1;

        while (true) {
            double ucr = u[cr];
            const float* crow = cost + cr * NQ;
            // relax
            #pragma unroll
            for (int s = 0; s < NSLOT; ++s) {
                int col = s * 32 + lane;
                bool ok = (s < 9 || valid9) && !((usedmask >> s) & 1u);
                if (ok) {
                    double cur = (double)crow[col] - ucr - vv[s];
                    if (cur < minv[s]) { minv[s] = cur; way[col] = j0; }
                }
            }
            // local argmin over slots (ascending col => first-index tiebreak)
            double bv = 1.0e300; int bi = 0x7fffffff;
            #pragma unroll
            for (int s = 0; s < NSLOT; ++s) {
                int col = s * 32 + lane;
                bool ok = (s < 9 || valid9) && !((usedmask >> s) & 1u);
                if (ok && minv[s] < bv) { bv = minv[s]; bi = col; }
            }
            // warp argmin (value, then smaller col)
            #pragma unroll
            for (int o = 16; o; o >>= 1) {
                double ov = __shfl_down_sync(0xffffffffu, bv, o);
                int oi = __shfl_down_sync(0xffffffffu, bi, o);
                if (ov < bv || (ov == bv && oi < bi)) { bv = ov; bi = oi; }
            }
            double delta = __shfl_sync(0xffffffffu, bv, 0);
            int j1 = __shfl_sync(0xffffffffu, bi, 0);

            // apply delta
            #pragma unroll
            for (int s = 0; s < NSLOT; ++s) {
                int col = s * 32 + lane;
                bool vld = (s < 9 || valid9);
                if (vld) {
                    if ((usedmask >> s) & 1u) {
                        u[p[col]] += delta;          // distinct rows per used col
                        vv[s] -= delta;
                    } else {
                        minv[s] -= delta;
                    }
                }
            }
            if (lane == 0) u[i] += delta;
            __syncwarp();

            if (lane == (j1 & 31)) usedmask |= 1u << (j1 >> 5);
            j0 = j1;
            cr = p[j1];
            if (cr == -1) break;
            __syncwarp();
        }

        __syncwarp();
        if (lane == 0) {
            int j = j0;
            while (j != -1) {
                int jp = way[j];
                p[j] = (jp != -1) ? p[jp] : i;
                j = jp;
            }
        }
        __syncwarp();
    }

    if (lane == 0 && out_size >= NB * NQ * NM + 2 * NB * NM) {
        float* pi = out + (size_t)NB * NQ * NM + (size_t)b * NM;
        float* gi = pi + (size_t)NB * NM;
        int r = 0;
        for (int j = 0; j < NQ; ++j)
            if (p[j] >= 0) { pi[r] = (float)j; gi[r] = (float)p[j]; ++r; }
    }
}

// ===================== launch =====================
extern "C" void kernel_launch(void* const* d_in, const int* in_sizes, int n_in,
                              void* d_out, int out_size) {
    const float* pred_logits = (const float*)d_in[0];
    const float* pred_boxes  = (const float*)d_in[1];
    const float* pred_masks  = (const float*)d_in[2];
    const int*   gt_labels   = (const int*)d_in[3];
    const float* gt_boxes    = (const float*)d_in[4];
    const float* gt_masks    = (const float*)d_in[5];
    float* out = (float*)d_out;

    k_convert_pred<<<NB * NQ, 256>>>(pred_masks);
    k_convert_gt<<<NB * NM, 256>>>(gt_masks);

    cudaFuncSetAttribute(k_mask_gemm, cudaFuncAttributeMaxDynamicSharedMemorySize, GEMM_SMEM);
    k_mask_gemm<<<dim3(3, NB, KSPLIT), 256, GEMM_SMEM>>>();

    k_finalize<<<dim3(NQ, NB), 128>>>(pred_logits, pred_boxes, gt_labels, gt_boxes, out);

    cudaFuncSetAttribute(k_hungarian, cudaFuncAttributeMaxDynamicSharedMemorySize, HUNG_SMEM);
    k_hungarian<<<NB, HUNG_THREADS, HUNG_SMEM>>>(out, out_size);
}

// round 4
// speedup vs baseline: 2.5868x; 2.5868x over previous
#include <cuda_runtime.h>
#include <cuda_bf16.h>
#include <cstdint>
#include <cstddef>

// ---------------- problem constants (fixed shapes) ----------------
#define NB 8
#define NQ 300
#define NM 100
#define NCLS 81
#define HW 16384
#define QPAD 384           // 3 tiles of 128 queries
#define MPAD 128           // gt padded to 128 for N dim
#define KSPLIT 4
#define KLEN (HW / KSPLIT) // 4096 bf16 per K-split
#define BK 64              // K tile (bf16 elems) = 128B row
#define KT (KLEN / BK)     // 64 iterations

// ---------------- static device scratch (no allocations allowed) ----------------
__device__ __nv_bfloat16 g_PM[(size_t)NB * QPAD * HW];   // sigmoid(pred_masks), bf16
__device__ __nv_bfloat16 g_GM[(size_t)NB * MPAD * HW];   // gt_masks, bf16
__device__ float g_NUM[(size_t)KSPLIT * NB * NQ * NM];   // partial dot products
__device__ float g_pm_sum[NB * NQ];
__device__ float g_gm_sum[NB * NM];

// ===================== kernel 1: sigmoid + bf16 convert + row sums =====================
__global__ void __launch_bounds__(256) k_convert_pred(const float* __restrict__ pm) {
    int bq = blockIdx.x;                       // 0..2399
    int b = bq / NQ, q = bq - b * NQ;
    const float4* src = reinterpret_cast<const float4*>(pm + (size_t)bq * HW);
    __nv_bfloat162* dst =
        reinterpret_cast<__nv_bfloat162*>(g_PM + ((size_t)b * QPAD + q) * HW);
    float sum = 0.f;
    for (int i = threadIdx.x; i < HW / 4; i += 256) {
        float4 v = src[i];
        float s0 = 1.f / (1.f + __expf(-v.x));
        float s1 = 1.f / (1.f + __expf(-v.y));
        float s2 = 1.f / (1.f + __expf(-v.z));
        float s3 = 1.f / (1.f + __expf(-v.w));
        sum += (s0 + s1) + (s2 + s3);
        dst[2 * i]     = __floats2bfloat162_rn(s0, s1);
        dst[2 * i + 1] = __floats2bfloat162_rn(s2, s3);
    }
    for (int o = 16; o; o >>= 1) sum += __shfl_down_sync(0xffffffffu, sum, o);
    __shared__ float ws[8];
    if ((threadIdx.x & 31) == 0) ws[threadIdx.x >> 5] = sum;
    __syncthreads();
    if (threadIdx.x == 0) {
        float t = 0.f;
        #pragma unroll
        for (int w = 0; w < 8; ++w) t += ws[w];
        g_pm_sum[bq] = t;
    }
}

__global__ void __launch_bounds__(256) k_convert_gt(const float* __restrict__ gm) {
    int bm = blockIdx.x;                       // 0..799
    int b = bm / NM, m = bm - b * NM;
    const float4* src = reinterpret_cast<const float4*>(gm + (size_t)bm * HW);
    __nv_bfloat162* dst =
        reinterpret_cast<__nv_bfloat162*>(g_GM + ((size_t)b * MPAD + m) * HW);
    float sum = 0.f;
    for (int i = threadIdx.x; i < HW / 4; i += 256) {
        float4 v = src[i];
        sum += (v.x + v.y) + (v.z + v.w);
        dst[2 * i]     = __floats2bfloat162_rn(v.x, v.y);
        dst[2 * i + 1] = __floats2bfloat162_rn(v.z, v.w);
    }
    for (int o = 16; o; o >>= 1) sum += __shfl_down_sync(0xffffffffu, sum, o);
    __shared__ float ws[8];
    if ((threadIdx.x & 31) == 0) ws[threadIdx.x >> 5] = sum;
    __syncthreads();
    if (threadIdx.x == 0) {
        float t = 0.f;
        #pragma unroll
        for (int w = 0; w < 8; ++w) t += ws[w];
        g_gm_sum[bm] = t;
    }
}

// ===================== kernel 2: mma.sync bf16 GEMM (dice numerator) =====================
#define TILE_BYTES 16384          // 128 rows x 128B
#define GEMM_SMEM (4 * TILE_BYTES)

__device__ __forceinline__ uint32_t sw128(uint32_t off) {
    return off ^ ((off >> 3) & 0x70);
}

__device__ __forceinline__ void cp_tile(const __nv_bfloat16* __restrict__ src,
                                        uint32_t dstBase) {
    int t = threadIdx.x;
    #pragma unroll
    for (int s = 0; s < 4; ++s) {
        int i = t + s * 256;                  // 0..1023
        int row = i >> 3, c16 = i & 7;
        unsigned long long g =
            __cvta_generic_to_global(src + (size_t)row * HW + c16 * 8);
        uint32_t off = sw128((uint32_t)(row * 128 + c16 * 16));
        asm volatile("cp.async.cg.shared.global [%0], [%1], 16;"
                     :: "r"(dstBase + off), "l"(g));
    }
}

__global__ void __launch_bounds__(256) k_mask_gemm() {
    extern __shared__ char smem[];
    uint32_t sA = (uint32_t)__cvta_generic_to_shared(smem);
    uint32_t sB = sA + 2 * TILE_BYTES;

    int tid = threadIdx.x, lane = tid & 31, warp = tid >> 5;
    int wm = warp & 1, wn = warp >> 1;        // 2 x 4 warp grid
    int warpRow = wm * 64, warpCol = wn * 32;

    int tile = blockIdx.x, b = blockIdx.y, ks = blockIdx.z;
    int q0 = tile * 128;

    const __nv_bfloat16* Abase = g_PM + ((size_t)b * QPAD + q0) * HW + (size_t)ks * KLEN;
    const __nv_bfloat16* Bbase = g_GM + (size_t)b * MPAD * HW + (size_t)ks * KLEN;

    float acc[4][4][4];
    #pragma unroll
    for (int i = 0; i < 4; ++i)
        #pragma unroll
        for (int j = 0; j < 4; ++j)
            #pragma unroll
            for (int r = 0; r < 4; ++r) acc[i][j][r] = 0.f;

    cp_tile(Abase, sA);
    cp_tile(Bbase, sB);
    asm volatile("cp.async.commit_group;");
    asm volatile("cp.async.wait_group 0;");
    __syncthreads();

    int rA = warpRow + (lane & 15);
    int cAsel = lane >> 4;
    int rB = warpCol + (lane & 7);
    int cBsel = (lane >> 3) & 1;

    int st = 0;
    for (int kt = 0; kt < KT; ++kt) {
        if (kt + 1 < KT) {
            int nst = st ^ 1;
            cp_tile(Abase + (size_t)(kt + 1) * BK, sA + nst * TILE_BYTES);
            cp_tile(Bbase + (size_t)(kt + 1) * BK, sB + nst * TILE_BYTES);
            asm volatile("cp.async.commit_group;");
        }
        uint32_t a0 = sA + st * TILE_BYTES;
        uint32_t b0 = sB + st * TILE_BYTES;

        #pragma unroll
        for (int kk = 0; kk < 4; ++kk) {
            uint32_t af[4][4], bf[4][2];
            #pragma unroll
            for (int mt = 0; mt < 4; ++mt) {
                uint32_t addr = a0 + sw128((uint32_t)((rA + mt * 16) * 128
                                                      + (kk * 2 + cAsel) * 16));
                asm volatile("ldmatrix.sync.aligned.m8n8.x4.shared.b16 "
                             "{%0,%1,%2,%3}, [%4];"
                             : "=r"(af[mt][0]), "=r"(af[mt][1]),
                               "=r"(af[mt][2]), "=r"(af[mt][3]) : "r"(addr));
            }
            #pragma unroll
            for (int nt = 0; nt < 4; ++nt) {
                uint32_t addr = b0 + sw128((uint32_t)((rB + nt * 8) * 128
                                                      + (kk * 2 + cBsel) * 16));
                asm volatile("ldmatrix.sync.aligned.m8n8.x2.shared.b16 "
                             "{%0,%1}, [%2];"
                             : "=r"(bf[nt][0]), "=r"(bf[nt][1]) : "r"(addr));
            }
            #pragma unroll
            for (int mt = 0; mt < 4; ++mt)
                #pragma unroll
                for (int nt = 0; nt < 4; ++nt) {
                    asm volatile(
                        "mma.sync.aligned.m16n8k16.row.col.f32.bf16.bf16.f32 "
                        "{%0,%1,%2,%3}, {%4,%5,%6,%7}, {%8,%9}, {%0,%1,%2,%3};"
                        : "+f"(acc[mt][nt][0]), "+f"(acc[mt][nt][1]),
                          "+f"(acc[mt][nt][2]), "+f"(acc[mt][nt][3])
                        : "r"(af[mt][0]), "r"(af[mt][1]),
                          "r"(af[mt][2]), "r"(af[mt][3]),
                          "r"(bf[nt][0]), "r"(bf[nt][1]));
                }
        }
        if (kt + 1 < KT) {
            asm volatile("cp.async.wait_group 0;");
        }
        __syncthreads();
        st ^= 1;
    }

    float* dst = g_NUM + ((size_t)ks * NB + b) * NQ * NM;
    int rowInTile = lane >> 2;
    int colInTile = (lane & 3) * 2;
    #pragma unroll
    for (int mt = 0; mt < 4; ++mt) {
        #pragma unroll
        for (int nt = 0; nt < 4; ++nt) {
            int qb = q0 + warpRow + mt * 16 + rowInTile;
            int mb = warpCol + nt * 8 + colInTile;
            #pragma unroll
            for (int r = 0; r < 4; ++r) {
                int q = qb + ((r >> 1) ? 8 : 0);
                int m = mb + (r & 1);
                if (q < NQ && m < NM)
                    dst[(size_t)q * NM + m] = acc[mt][nt][r];
            }
        }
    }
}

// ===================== kernel 3: assemble full cost matrix =====================
__global__ void __launch_bounds__(128) k_finalize(const float* __restrict__ logits,
                                                  const float* __restrict__ pboxes,
                                                  const int* __restrict__ glabels,
                                                  const float* __restrict__ gboxes,
                                                  float* __restrict__ out) {
    int q = blockIdx.x, b = blockIdx.y;
    int tid = threadIdx.x;
    __shared__ float probs[NCLS];
    __shared__ float red[128];

    const float* lg = logits + ((size_t)b * NQ + q) * NCLS;
    float x = (tid < NCLS) ? lg[tid] : -3.0e38f;
    red[tid] = x; __syncthreads();
    #pragma unroll
    for (int s = 64; s > 0; s >>= 1) { if (tid < s) red[tid] = fmaxf(red[tid], red[tid + s]); __syncthreads(); }
    float mx = red[0]; __syncthreads();
    float e = (tid < NCLS) ? __expf(x - mx) : 0.f;
    red[tid] = e; __syncthreads();
    #pragma unroll
    for (int s = 64; s > 0; s >>= 1) { if (tid < s) red[tid] += red[tid + s]; __syncthreads(); }
    float inv = 1.f / red[0];
    if (tid < NCLS) probs[tid] = e * inv;
    __syncthreads();

    const float* pb = pboxes + ((size_t)b * NQ + q) * 4;
    float px1 = pb[0], py1 = pb[1], px2 = pb[2], py2 = pb[3];
    float pa = (px2 - px1) * (py2 - py1);
    float psum = g_pm_sum[b * NQ + q];
    const size_t NSTR = (size_t)NB * NQ * NM;

    for (int m = tid; m < NM; m += 128) {
        int lbl = glabels[b * NM + m];
        float cclass = -probs[lbl];
        const float* gb = gboxes + ((size_t)b * NM + m) * 4;
        float gx1 = gb[0], gy1 = gb[1], gx2 = gb[2], gy2 = gb[3];
        float l1 = fabsf(px1 - gx1) + fabsf(py1 - gy1) + fabsf(px2 - gx2) + fabsf(py2 - gy2);
        float iw = fmaxf(fminf(px2, gx2) - fmaxf(px1, gx1), 0.f);
        float ih = fmaxf(fminf(py2, gy2) - fmaxf(py1, gy1), 0.f);
        float inter = iw * ih;
        float ga = (gx2 - gx1) * (gy2 - gy1);
        float uni = pa + ga - inter;
        float iou = inter / (uni + 1e-6f);
        float ew = fmaxf(fmaxf(px2, gx2) - fminf(px1, gx1), 0.f);
        float eh = fmaxf(fmaxf(py2, gy2) - fminf(py1, gy1), 0.f);
        float am = ew * eh;
        float giou = iou - (am - uni) / (am + 1e-6f);
        size_t ni = ((size_t)b * NQ + q) * NM + m;
        float dot = g_NUM[ni] + g_NUM[NSTR + ni] + g_NUM[2 * NSTR + ni] + g_NUM[3 * NSTR + ni];
        float den = psum + g_gm_sum[b * NM + m];
        float cmask = 1.f - (2.f * dot) / (den + 1e-6f);
        out[ni] = cclass + 5.f * (l1 - giou) + 2.f * cmask;
    }
}

// ===================== kernel 4: single-warp JV, f32 + redux argmin =====================
// Shared: u[100] f32, cost[100][300] f32 (transposed), p[300], way[300], rowdone[100].
#define HUNG_THREADS 512
#define HUNG_SMEM (NM * 4 + NM * NQ * 4 + NQ * 4 * 2 + NM * 4)
#define NSLOT 10

__device__ __forceinline__ uint32_t fkey(float f) {
    uint32_t u = __float_as_uint(f);
    return (u & 0x80000000u) ? ~u : (u | 0x80000000u);
}
__device__ __forceinline__ float funkey(uint32_t k) {
    uint32_t u = (k & 0x80000000u) ? (k & 0x7fffffffu) : ~k;
    return __uint_as_float(u);
}
__device__ __forceinline__ uint32_t redux_min(uint32_t v) {
    uint32_t d;
    asm volatile("redux.sync.min.u32 %0, %1, 0xffffffff;" : "=r"(d) : "r"(v));
    return d;
}

__global__ void __launch_bounds__(HUNG_THREADS) k_hungarian(float* __restrict__ out, int out_size) {
    extern __shared__ char sm[];
    float* u    = reinterpret_cast<float*>(sm);               // [100]
    float* cost = u + NM;                                     // [100][300]
    int* p      = reinterpret_cast<int*>(cost + NM * NQ);     // [300]
    int* way    = p + NQ;                                     // [300]
    int* rowdone = way + NQ;                                  // [100]

    int b = blockIdx.x;
    int tid = threadIdx.x;
    const float* C = out + (size_t)b * NQ * NM;

    // cooperative transpose load: cost[m][q] = C[q][m]
    for (int idx = tid; idx < NM * NQ; idx += HUNG_THREADS) {
        int q = idx / NM, m = idx - q * NM;
        cost[m * NQ + q] = C[idx];
    }
    for (int j = tid; j < NQ; j += HUNG_THREADS) p[j] = -1;
    __syncthreads();
    if (tid >= 32) return;

    const int lane = tid;
    const bool valid9 = (lane < 12);          // col 288..299 only

    float vv[NSLOT], minv[NSLOT];
    #pragma unroll
    for (int s = 0; s < NSLOT; ++s) vv[s] = 0.0f;

    // ---- row reduction + greedy seed ----
    for (int i = 0; i < NM; ++i) {
        const float* crow = cost + i * NQ;
        uint32_t bk = 0xffffffffu; int bi = 0x7fffffff;
        #pragma unroll
        for (int s = 0; s < NSLOT; ++s) {
            int col = s * 32 + lane;
            if (s < 9 || valid9) {
                uint32_t k = fkey(crow[col]);
                if (k < bk) { bk = k; bi = col; }
            }
        }
        uint32_t mk = redux_min(bk);
        uint32_t cand = (bk == mk) ? (uint32_t)bi : 0xffffffffu;
        uint32_t jstar = redux_min(cand);
        if (lane == 0) {
            u[i] = funkey(mk);
            if (p[jstar] == -1) { p[jstar] = i; rowdone[i] = 1; }
            else rowdone[i] = 0;
        }
    }
    __syncwarp();

    // ---- augment remaining rows (shortest augmenting path, f32 duals) ----
    for (int i = 0; i < NM; ++i) {
        if (rowdone[i]) continue;
        unsigned usedmask = 0;
        #pragma unroll
        for (int s = 0; s < NSLOT; ++s) minv[s] = 3.0e38f;
        int cr = i, j0 = -1;

        while (true) {
            float ucr = u[cr];
            const float* crow = cost + cr * NQ;
            uint32_t bk = 0xffffffffu; int bi = 0x7fffffff;
            #pragma unroll
            for (int s = 0; s < NSLOT; ++s) {
                int col = s * 32 + lane;
                bool ok = (s < 9 || valid9) && !((usedmask >> s) & 1u);
                if (ok) {
                    float cur = crow[col] - ucr - vv[s];
                    if (cur < minv[s]) { minv[s] = cur; way[col] = j0; }
                    uint32_t k = fkey(minv[s]);
                    if (k < bk) { bk = k; bi = col; }
                }
            }
            uint32_t mk = redux_min(bk);
            float delta = funkey(mk);
            uint32_t cand = (bk == mk) ? (uint32_t)bi : 0xffffffffu;
            int j1 = (int)redux_min(cand);

            #pragma unroll
            for (int s = 0; s < NSLOT; ++s) {
                int col = s * 32 + lane;
                if (s < 9 || valid9) {
                    if ((usedmask >> s) & 1u) {
                        u[p[col]] += delta;       // distinct rows per used col
                        vv[s] -= delta;
                    } else {
                        minv[s] -= delta;
                    }
                }
            }
            if (lane == 0) u[i] += delta;
            __syncwarp();

            if (lane == (j1 & 31)) usedmask |= 1u << (j1 >> 5);
            j0 = j1;
            cr = p[j1];
            if (cr == -1) break;
            __syncwarp();
        }

        __syncwarp();
        if (lane == 0) {
            int j = j0;
            while (j != -1) {
                int jp = way[j];
                p[j] = (jp != -1) ? p[jp] : i;
                j = jp;
            }
        }
        __syncwarp();
    }

    if (lane == 0 && out_size >= NB * NQ * NM + 2 * NB * NM) {
        float* pi = out + (size_t)NB * NQ * NM + (size_t)b * NM;
        float* gi = pi + (size_t)NB * NM;
        int r = 0;
        for (int j = 0; j < NQ; ++j)
            if (p[j] >= 0) { pi[r] = (float)j; gi[r] = (float)p[j]; ++r; }
    }
}

// ===================== launch =====================
extern "C" void kernel_launch(void* const* d_in, const int* in_sizes, int n_in,
                              void* d_out, int out_size) {
    const float* pred_logits = (const float*)d_in[0];
    const float* pred_boxes  = (const float*)d_in[1];
    const float* pred_masks  = (const float*)d_in[2];
    const int*   gt_labels   = (const int*)d_in[3];
    const float* gt_boxes    = (const float*)d_in[4];
    const float* gt_masks    = (const float*)d_in[5];
    float* out = (float*)d_out;

    k_convert_pred<<<NB * NQ, 256>>>(pred_masks);
    k_convert_gt<<<NB * NM, 256>>>(gt_masks);

    cudaFuncSetAttribute(k_mask_gemm, cudaFuncAttributeMaxDynamicSharedMemorySize, GEMM_SMEM);
    k_mask_gemm<<<dim3(3, NB, KSPLIT), 256, GEMM_SMEM>>>();

    k_finalize<<<dim3(NQ, NB), 128>>>(pred_logits, pred_boxes, gt_labels, gt_boxes, out);

    cudaFuncSetAttribute(k_hungarian, cudaFuncAttributeMaxDynamicSharedMemorySize, HUNG_SMEM);
    k_hungarian<<<NB, HUNG_THREADS, HUNG_SMEM>>>(out, out_size);
}